// round 5
// baseline (speedup 1.0000x reference)
#include <cuda_runtime.h>

// x:   [B, N, 128] f32  -> viewed as [B*N, 32] float4
// R:   [B, N, 2, 2] f32 -> viewed as [B*N] float4 (r00, r01, r10, r11)
// y0 = r00*x0 + r01*x1 ; y1 = r10*x0 + r11*x1 per consecutive pair.
//
// Persistent grid-stride: exactly one resident wave (1184 CTAs = 148 SMs x
// occ 8; also single-wave on 152-SM GB300). Each warp loops over the stream
// with stride gridDim*blockDim -- every access stays perfectly coalesced,
// and the unrolled loop keeps 2 independent LDG.128 in flight continuously
// instead of paying cold-start latency per CTA across ~28 waves.

#define THREADS 256
#define BLOCKS  1184

__global__ __launch_bounds__(THREADS) void rot2_kernel(
    const float4* __restrict__ x,
    const float4* __restrict__ R,
    float4* __restrict__ out,
    int n4)
{
    const int stride = BLOCKS * THREADS;
    int i = blockIdx.x * THREADS + threadIdx.x;

    // Main loop: unroll 2 for steady-state MLP without register blowup.
#pragma unroll 2
    for (; i < n4; i += stride) {
        float4 r = __ldg(&R[i >> 5]);   // 32 float4 per point; warp broadcast
        float4 v = __ldcs(&x[i]);       // streaming read, evict-first

        float4 o;
        o.x = fmaf(r.x, v.x, r.y * v.y);
        o.y = fmaf(r.z, v.x, r.w * v.y);
        o.z = fmaf(r.x, v.z, r.y * v.w);
        o.w = fmaf(r.z, v.z, r.w * v.w);
        __stcs(&out[i], o);             // streaming write, evict-first
    }
}

extern "C" void kernel_launch(void* const* d_in, const int* in_sizes, int n_in,
                              void* d_out, int out_size)
{
    const float4* x = (const float4*)d_in[0];
    const float4* R = (const float4*)d_in[1];
    float4* out = (float4*)d_out;

    int n4 = out_size / 4;              // 8,388,608 float4
    rot2_kernel<<<BLOCKS, THREADS>>>(x, R, out, n4);
}

// round 6
// speedup vs baseline: 1.0092x; 1.0092x over previous
#include <cuda_runtime.h>

// x:   [B, N, 128] f32 ; R: [B, N, 2, 2] f32 (r00, r01, r10, r11 per point)
// y0 = r00*x0 + r01*x1 ; y1 = r10*x0 + r11*x1 per consecutive pair.
//
// 256-bit path (sm_100+): each thread moves one 32B chunk (8 floats = 4
// rotated pairs) via ld.global.v8.f32 / st.global.v8.f32. Lanes hold
// consecutive 32B chunks -> each warp instruction covers 1024B densely
// (8 full 128B lines, no holes). Halves LSU ops and L2 requests vs the
// 128-bit version. 16 consecutive lanes share one R (L1 broadcast).

__global__ __launch_bounds__(256) void rot2_kernel(
    const float* __restrict__ x,
    const float4* __restrict__ R,
    float* __restrict__ out,
    int n8)   // number of 8-float chunks
{
    int t = blockIdx.x * blockDim.x + threadIdx.x;
    if (t >= n8) return;

    // 128 floats per point = 16 chunks per point
    float4 r = __ldg(&R[t >> 4]);

    const float* px = x   + ((size_t)t << 3);
    float*       po = out + ((size_t)t << 3);

    float a0, a1, a2, a3, a4, a5, a6, a7;
    asm volatile(
        "ld.global.v8.f32 {%0,%1,%2,%3,%4,%5,%6,%7}, [%8];"
        : "=f"(a0), "=f"(a1), "=f"(a2), "=f"(a3),
          "=f"(a4), "=f"(a5), "=f"(a6), "=f"(a7)
        : "l"(px));

    float o0 = fmaf(r.x, a0, r.y * a1);
    float o1 = fmaf(r.z, a0, r.w * a1);
    float o2 = fmaf(r.x, a2, r.y * a3);
    float o3 = fmaf(r.z, a2, r.w * a3);
    float o4 = fmaf(r.x, a4, r.y * a5);
    float o5 = fmaf(r.z, a4, r.w * a5);
    float o6 = fmaf(r.x, a6, r.y * a7);
    float o7 = fmaf(r.z, a6, r.w * a7);

    asm volatile(
        "st.global.v8.f32 [%0], {%1,%2,%3,%4,%5,%6,%7,%8};"
        :: "l"(po),
           "f"(o0), "f"(o1), "f"(o2), "f"(o3),
           "f"(o4), "f"(o5), "f"(o6), "f"(o7)
        : "memory");
}

extern "C" void kernel_launch(void* const* d_in, const int* in_sizes, int n_in,
                              void* d_out, int out_size)
{
    const float*  x = (const float*)d_in[0];
    const float4* R = (const float4*)d_in[1];
    float* out = (float*)d_out;

    int n8 = out_size / 8;              // 4,194,304 chunks of 8 floats
    int threads = 256;
    int blocks = (n8 + threads - 1) / threads;
    rot2_kernel<<<blocks, threads>>>(x, R, out, n8);
}